// round 12
// baseline (speedup 1.0000x reference)
#include <cuda_runtime.h>
#include <cstdint>

typedef unsigned long long u64;

#define RS_STRIDE 128   // floats per row of rs[32][RS_STRIDE]

// ---------------- packed f32x2 helpers ----------------
__device__ __forceinline__ u64 pack2(float lo, float hi) {
    u64 r; asm("mov.b64 %0, {%1,%2};" : "=l"(r) : "f"(lo), "f"(hi)); return r;
}
__device__ __forceinline__ void unpack2(u64 v, float& lo, float& hi) {
    asm("mov.b64 {%0,%1}, %2;" : "=f"(lo), "=f"(hi) : "l"(v));
}
__device__ __forceinline__ u64 fma2(u64 a, u64 b, u64 c) {
    u64 d; asm("fma.rn.f32x2 %0, %1, %2, %3;" : "=l"(d) : "l"(a), "l"(b), "l"(c)); return d;
}
__device__ __forceinline__ u64 mul2(u64 a, u64 b) {
    u64 d; asm("mul.rn.f32x2 %0, %1, %2;" : "=l"(d) : "l"(a), "l"(b)); return d;
}
__device__ __forceinline__ void lds_v2u64(u64& a, u64& b, uint32_t addr) {
    asm volatile("ld.shared.v2.u64 {%0,%1}, [%2];" : "=l"(a), "=l"(b) : "r"(addr));
}

__device__ __forceinline__ float ssqrt(float y) {
    float r = sqrtf(fabsf(y) + 1e-6f);
    return y > 0.0f ? r : (y < 0.0f ? -r : 0.0f);
}

// Shapes: x[8,256,96,96], w_reduce[32,256], w_recover[256,528], out[8,256,96,96]
// HW = 9216 = 72 * 128 pixel tiles per image; grid = 8*72 = 576 CTAs of 256 threads.
__global__ __launch_bounds__(256, 2)
void bilinear_gate_kernel(const float* __restrict__ x,
                          const float* __restrict__ w_reduce,
                          const float* __restrict__ w_recover,
                          float* __restrict__ out)
{
    __shared__ __align__(16) float rs[32][RS_STRIDE];   // reduced features, r-major
    __shared__ __align__(16) union {
        float wt[16][128];   // stage C: w_recover chunk, [kk][o_local]
        float wc[32][64];    // stage 1: w_reduce chunk, [r][c_local]
    } u;
    __shared__ int ioff[528];   // byte offset of row i in rs
    __shared__ int joff[528];   // byte offset of row j in rs

    const int tid  = threadIdx.x;
    const int tile = blockIdx.x;          // 0..575
    const int b    = tile / 72;
    const int hw0  = (tile % 72) * 128;

    // ---- build triu (i,j) offset tables (once per CTA, trivial cost) ----
    for (int k = tid; k < 528; k += 256) {
        int i = 0;
        while (i < 31 && ((65 * (i + 1) - (i + 1) * (i + 1)) >> 1) <= k) ++i;
        int j = i + (k - ((65 * i - i * i) >> 1));
        ioff[k] = i * (RS_STRIDE * 4);
        joff[k] = j * (RS_STRIDE * 4);
    }

    // ================= Stage 1: rs[r][p] = sum_c w_reduce[r][c] * x[b,c,p] =================
    {
        const int p     = tid & 127;
        const int chalf = tid >> 7;        // split 256 channels: half 0 -> c%64<32, half 1 -> upper
        const float* xb = x + ((size_t)b * 256) * 9216 + hw0;

        u64 acc1[32];
#pragma unroll
        for (int r = 0; r < 32; ++r) acc1[r] = 0ULL;

        for (int c0 = 0; c0 < 256; c0 += 64) {
            __syncthreads();
            {   // cooperative load of w_reduce[0..31][c0..c0+63] -> u.wc
                int r   = tid >> 3;            // 0..31
                int cof = (tid & 7) * 8;       // 0..56
                const float* src = w_reduce + r * 256 + c0 + cof;
                float4 w0 = *(const float4*)src;
                float4 w1 = *(const float4*)(src + 4);
                *(float4*)&u.wc[r][cof]     = w0;
                *(float4*)&u.wc[r][cof + 4] = w1;
            }
            __syncthreads();
            const int ccb = chalf * 32;
#pragma unroll 4
            for (int cc = 0; cc < 32; cc += 2) {
                float x0 = xb[(size_t)(c0 + ccb + cc) * 9216 + p];
                float x1 = xb[(size_t)(c0 + ccb + cc + 1) * 9216 + p];
                u64 xp = pack2(x0, x1);
#pragma unroll
                for (int r = 0; r < 32; ++r)
                    acc1[r] = fma2(xp, *(const u64*)&u.wc[r][ccb + cc], acc1[r]);
            }
        }
        __syncthreads();
        if (chalf == 0) {
#pragma unroll
            for (int r = 0; r < 32; ++r) {
                float lo, hi; unpack2(acc1[r], lo, hi);
                rs[r][p] = lo + hi;
            }
        }
        __syncthreads();
        if (chalf == 1) {
#pragma unroll
            for (int r = 0; r < 32; ++r) {
                float lo, hi; unpack2(acc1[r], lo, hi);
                rs[r][p] += lo + hi;
            }
        }
        // rs is made visible by the __syncthreads() at the top of the chunk loop below
    }

    // ================= Stage C: y[p][o] = sum_k w_recover[o][k] * r_i(k) * r_j(k) =================
    const int pr = tid >> 4;            // 0..15  -> pixels pr*8 .. pr*8+7
    const int oq = tid & 15;            // 0..15  -> outputs oq*8 .. oq*8+7 (within 128-half)
    const int p0 = pr * 8;
    const uint32_t rs_sh = (uint32_t)__cvta_generic_to_shared(&rs[0][0]) + (uint32_t)(p0 * 4);
    float* yb = out + ((size_t)b * 256) * 9216 + hw0;

    for (int halfo = 0; halfo < 2; ++halfo) {
        const int o_base = halfo * 128;

        u64 acc[8][4];
#pragma unroll
        for (int oo = 0; oo < 8; ++oo)
#pragma unroll
            for (int q = 0; q < 4; ++q) acc[oo][q] = 0ULL;

        // each thread streams 8 consecutive k of one o-row per chunk
        const float* wr = w_recover + (size_t)(o_base + (tid >> 1)) * 528 + (size_t)((tid & 1) * 8);
        float4 pf0 = *(const float4*)(wr);
        float4 pf1 = *(const float4*)(wr + 4);

        for (int ch = 0; ch < 33; ++ch) {        // 33 * 16 = 528
            __syncthreads();                     // previous chunk's compute finished
            {   // store prefetched chunk (transposed: wt[kk][o_local])
                const int kkb = (tid & 1) * 8;
                const int oc  = tid >> 1;
                u.wt[kkb + 0][oc] = pf0.x; u.wt[kkb + 1][oc] = pf0.y;
                u.wt[kkb + 2][oc] = pf0.z; u.wt[kkb + 3][oc] = pf0.w;
                u.wt[kkb + 4][oc] = pf1.x; u.wt[kkb + 5][oc] = pf1.y;
                u.wt[kkb + 6][oc] = pf1.z; u.wt[kkb + 7][oc] = pf1.w;
            }
            if (ch < 32) {                        // prefetch next chunk into registers
                pf0 = *(const float4*)(wr + (ch + 1) * 16);
                pf1 = *(const float4*)(wr + (ch + 1) * 16 + 4);
            }
            __syncthreads();

            const int kbase = ch * 16;
#pragma unroll
            for (int kk = 0; kk < 16; ++kk) {
                const int k  = kbase + kk;
                const int io = ioff[k];
                const int jo = joff[k];
                u64 ri0, ri1, ri2, ri3, rj0, rj1, rj2, rj3;
                lds_v2u64(ri0, ri1, rs_sh + io);
                lds_v2u64(ri2, ri3, rs_sh + io + 16);
                lds_v2u64(rj0, rj1, rs_sh + jo);
                lds_v2u64(rj2, rj3, rs_sh + jo + 16);
                u64 a0 = mul2(ri0, rj0);
                u64 a1 = mul2(ri1, rj1);
                u64 a2 = mul2(ri2, rj2);
                u64 a3 = mul2(ri3, rj3);
                const float4 b0 = *(const float4*)&u.wt[kk][oq * 8];
                const float4 b1 = *(const float4*)&u.wt[kk][oq * 8 + 4];
#define FMA_OO(oo, bval) { u64 w2 = pack2((bval), (bval)); \
                acc[oo][0] = fma2(a0, w2, acc[oo][0]); \
                acc[oo][1] = fma2(a1, w2, acc[oo][1]); \
                acc[oo][2] = fma2(a2, w2, acc[oo][2]); \
                acc[oo][3] = fma2(a3, w2, acc[oo][3]); }
                FMA_OO(0, b0.x) FMA_OO(1, b0.y) FMA_OO(2, b0.z) FMA_OO(3, b0.w)
                FMA_OO(4, b1.x) FMA_OO(5, b1.y) FMA_OO(6, b1.z) FMA_OO(7, b1.w)
#undef FMA_OO
            }
        }

        // ---- epilogue: signed sqrt + store 8 pixels x 8 outputs ----
#pragma unroll
        for (int oo = 0; oo < 8; ++oo) {
            const int o = o_base + oq * 8 + oo;
            float f[8];
#pragma unroll
            for (int q = 0; q < 4; ++q) {
                float lo, hi; unpack2(acc[oo][q], lo, hi);
                f[2 * q]     = ssqrt(lo);
                f[2 * q + 1] = ssqrt(hi);
            }
            float* dst = yb + (size_t)o * 9216 + p0;
            *(float4*)dst       = make_float4(f[0], f[1], f[2], f[3]);
            *(float4*)(dst + 4) = make_float4(f[4], f[5], f[6], f[7]);
        }
    }
}

extern "C" void kernel_launch(void* const* d_in, const int* in_sizes, int n_in,
                              void* d_out, int out_size)
{
    // Map inputs by element count (defensive against ordering surprises):
    // x: 8*256*96*96 = 18874368, w_reduce: 32*256 = 8192, w_recover: 256*528 = 135168
    const float* x = nullptr;
    const float* w_reduce = nullptr;
    const float* w_recover = nullptr;
    for (int t = 0; t < n_in; ++t) {
        if (in_sizes[t] == 8 * 256 * 96 * 96)      x = (const float*)d_in[t];
        else if (in_sizes[t] == 32 * 256)          w_reduce = (const float*)d_in[t];
        else if (in_sizes[t] == 256 * 528)         w_recover = (const float*)d_in[t];
    }
    if (!x) x = (const float*)d_in[0];
    if (!w_reduce) w_reduce = (const float*)d_in[1];
    if (!w_recover) w_recover = (const float*)d_in[2];

    float* out = (float*)d_out;
    bilinear_gate_kernel<<<576, 256>>>(x, w_reduce, w_recover, out);
}

// round 13
// speedup vs baseline: 1.0001x; 1.0001x over previous
#include <cuda_runtime.h>
#include <cstdint>

typedef unsigned long long u64;

#define RS_STRIDE 128   // floats per row of rs[32][RS_STRIDE]

// ---------------- packed f32x2 helpers ----------------
__device__ __forceinline__ u64 pack2(float lo, float hi) {
    u64 r; asm("mov.b64 %0, {%1,%2};" : "=l"(r) : "f"(lo), "f"(hi)); return r;
}
__device__ __forceinline__ void unpack2(u64 v, float& lo, float& hi) {
    asm("mov.b64 {%0,%1}, %2;" : "=f"(lo), "=f"(hi) : "l"(v));
}
__device__ __forceinline__ u64 fma2(u64 a, u64 b, u64 c) {
    u64 d; asm("fma.rn.f32x2 %0, %1, %2, %3;" : "=l"(d) : "l"(a), "l"(b), "l"(c)); return d;
}
__device__ __forceinline__ u64 mul2(u64 a, u64 b) {
    u64 d; asm("mul.rn.f32x2 %0, %1, %2;" : "=l"(d) : "l"(a), "l"(b)); return d;
}
__device__ __forceinline__ void lds_v2u64(u64& a, u64& b, uint32_t addr) {
    asm volatile("ld.shared.v2.u64 {%0,%1}, [%2];" : "=l"(a), "=l"(b) : "r"(addr));
}

__device__ __forceinline__ float ssqrt(float y) {
    float r = sqrtf(fabsf(y) + 1e-6f);
    return y > 0.0f ? r : (y < 0.0f ? -r : 0.0f);
}

// Shapes: x[8,256,96,96], w_reduce[32,256], w_recover[256,528], out[8,256,96,96]
// HW = 9216 = 72 * 128 pixel tiles per image; grid = 8*72 = 576 CTAs of 256 threads.
__global__ __launch_bounds__(256, 2)
void bilinear_gate_kernel(const float* __restrict__ x,
                          const float* __restrict__ w_reduce,
                          const float* __restrict__ w_recover,
                          float* __restrict__ out)
{
    __shared__ __align__(16) float rs[32][RS_STRIDE];   // reduced features, r-major
    __shared__ __align__(16) union {
        float wt[16][128];   // stage C: w_recover chunk, [kk][o_local]
        float wc[32][64];    // stage 1: w_reduce chunk, [r][c_local]
    } u;
    __shared__ int ioff[528];   // byte offset of row i in rs
    __shared__ int joff[528];   // byte offset of row j in rs

    const int tid  = threadIdx.x;
    const int tile = blockIdx.x;          // 0..575
    const int b    = tile / 72;
    const int hw0  = (tile % 72) * 128;

    // ---- build triu (i,j) offset tables (once per CTA, trivial cost) ----
    for (int k = tid; k < 528; k += 256) {
        int i = 0;
        while (i < 31 && ((65 * (i + 1) - (i + 1) * (i + 1)) >> 1) <= k) ++i;
        int j = i + (k - ((65 * i - i * i) >> 1));
        ioff[k] = i * (RS_STRIDE * 4);
        joff[k] = j * (RS_STRIDE * 4);
    }

    // ================= Stage 1: rs[r][p] = sum_c w_reduce[r][c] * x[b,c,p] =================
    {
        const int p     = tid & 127;
        const int chalf = tid >> 7;        // split 256 channels: half 0 -> c%64<32, half 1 -> upper
        const float* xb = x + ((size_t)b * 256) * 9216 + hw0;

        u64 acc1[32];
#pragma unroll
        for (int r = 0; r < 32; ++r) acc1[r] = 0ULL;

        for (int c0 = 0; c0 < 256; c0 += 64) {
            __syncthreads();
            {   // cooperative load of w_reduce[0..31][c0..c0+63] -> u.wc
                int r   = tid >> 3;            // 0..31
                int cof = (tid & 7) * 8;       // 0..56
                const float* src = w_reduce + r * 256 + c0 + cof;
                float4 w0 = *(const float4*)src;
                float4 w1 = *(const float4*)(src + 4);
                *(float4*)&u.wc[r][cof]     = w0;
                *(float4*)&u.wc[r][cof + 4] = w1;
            }
            __syncthreads();
            const int ccb = chalf * 32;
#pragma unroll 4
            for (int cc = 0; cc < 32; cc += 2) {
                float x0 = xb[(size_t)(c0 + ccb + cc) * 9216 + p];
                float x1 = xb[(size_t)(c0 + ccb + cc + 1) * 9216 + p];
                u64 xp = pack2(x0, x1);
#pragma unroll
                for (int r = 0; r < 32; ++r)
                    acc1[r] = fma2(xp, *(const u64*)&u.wc[r][ccb + cc], acc1[r]);
            }
        }
        __syncthreads();
        if (chalf == 0) {
#pragma unroll
            for (int r = 0; r < 32; ++r) {
                float lo, hi; unpack2(acc1[r], lo, hi);
                rs[r][p] = lo + hi;
            }
        }
        __syncthreads();
        if (chalf == 1) {
#pragma unroll
            for (int r = 0; r < 32; ++r) {
                float lo, hi; unpack2(acc1[r], lo, hi);
                rs[r][p] += lo + hi;
            }
        }
        // rs is made visible by the __syncthreads() at the top of the chunk loop below
    }

    // ================= Stage C: y[p][o] = sum_k w_recover[o][k] * r_i(k) * r_j(k) =================
    const int pr = tid >> 4;            // 0..15  -> pixels pr*8 .. pr*8+7
    const int oq = tid & 15;            // 0..15  -> outputs oq*8 .. oq*8+7 (within 128-half)
    const int p0 = pr * 8;
    const uint32_t rs_sh = (uint32_t)__cvta_generic_to_shared(&rs[0][0]) + (uint32_t)(p0 * 4);
    float* yb = out + ((size_t)b * 256) * 9216 + hw0;

    for (int halfo = 0; halfo < 2; ++halfo) {
        const int o_base = halfo * 128;

        u64 acc[8][4];
#pragma unroll
        for (int oo = 0; oo < 8; ++oo)
#pragma unroll
            for (int q = 0; q < 4; ++q) acc[oo][q] = 0ULL;

        // each thread streams 8 consecutive k of one o-row per chunk
        const float* wr = w_recover + (size_t)(o_base + (tid >> 1)) * 528 + (size_t)((tid & 1) * 8);
        float4 pf0 = *(const float4*)(wr);
        float4 pf1 = *(const float4*)(wr + 4);

        for (int ch = 0; ch < 33; ++ch) {        // 33 * 16 = 528
            __syncthreads();                     // previous chunk's compute finished
            {   // store prefetched chunk (transposed: wt[kk][o_local])
                const int kkb = (tid & 1) * 8;
                const int oc  = tid >> 1;
                u.wt[kkb + 0][oc] = pf0.x; u.wt[kkb + 1][oc] = pf0.y;
                u.wt[kkb + 2][oc] = pf0.z; u.wt[kkb + 3][oc] = pf0.w;
                u.wt[kkb + 4][oc] = pf1.x; u.wt[kkb + 5][oc] = pf1.y;
                u.wt[kkb + 6][oc] = pf1.z; u.wt[kkb + 7][oc] = pf1.w;
            }
            if (ch < 32) {                        // prefetch next chunk into registers
                pf0 = *(const float4*)(wr + (ch + 1) * 16);
                pf1 = *(const float4*)(wr + (ch + 1) * 16 + 4);
            }
            __syncthreads();

            const int kbase = ch * 16;
#pragma unroll
            for (int kk = 0; kk < 16; ++kk) {
                const int k  = kbase + kk;
                const int io = ioff[k];
                const int jo = joff[k];
                u64 ri0, ri1, ri2, ri3, rj0, rj1, rj2, rj3;
                lds_v2u64(ri0, ri1, rs_sh + io);
                lds_v2u64(ri2, ri3, rs_sh + io + 16);
                lds_v2u64(rj0, rj1, rs_sh + jo);
                lds_v2u64(rj2, rj3, rs_sh + jo + 16);
                u64 a0 = mul2(ri0, rj0);
                u64 a1 = mul2(ri1, rj1);
                u64 a2 = mul2(ri2, rj2);
                u64 a3 = mul2(ri3, rj3);
                const float4 b0 = *(const float4*)&u.wt[kk][oq * 8];
                const float4 b1 = *(const float4*)&u.wt[kk][oq * 8 + 4];
#define FMA_OO(oo, bval) { u64 w2 = pack2((bval), (bval)); \
                acc[oo][0] = fma2(a0, w2, acc[oo][0]); \
                acc[oo][1] = fma2(a1, w2, acc[oo][1]); \
                acc[oo][2] = fma2(a2, w2, acc[oo][2]); \
                acc[oo][3] = fma2(a3, w2, acc[oo][3]); }
                FMA_OO(0, b0.x) FMA_OO(1, b0.y) FMA_OO(2, b0.z) FMA_OO(3, b0.w)
                FMA_OO(4, b1.x) FMA_OO(5, b1.y) FMA_OO(6, b1.z) FMA_OO(7, b1.w)
#undef FMA_OO
            }
        }

        // ---- epilogue: signed sqrt + store 8 pixels x 8 outputs ----
#pragma unroll
        for (int oo = 0; oo < 8; ++oo) {
            const int o = o_base + oq * 8 + oo;
            float f[8];
#pragma unroll
            for (int q = 0; q < 4; ++q) {
                float lo, hi; unpack2(acc[oo][q], lo, hi);
                f[2 * q]     = ssqrt(lo);
                f[2 * q + 1] = ssqrt(hi);
            }
            float* dst = yb + (size_t)o * 9216 + p0;
            *(float4*)dst       = make_float4(f[0], f[1], f[2], f[3]);
            *(float4*)(dst + 4) = make_float4(f[4], f[5], f[6], f[7]);
        }
    }
}

extern "C" void kernel_launch(void* const* d_in, const int* in_sizes, int n_in,
                              void* d_out, int out_size)
{
    // Map inputs by element count (defensive against ordering surprises):
    // x: 8*256*96*96 = 18874368, w_reduce: 32*256 = 8192, w_recover: 256*528 = 135168
    const float* x = nullptr;
    const float* w_reduce = nullptr;
    const float* w_recover = nullptr;
    for (int t = 0; t < n_in; ++t) {
        if (in_sizes[t] == 8 * 256 * 96 * 96)      x = (const float*)d_in[t];
        else if (in_sizes[t] == 32 * 256)          w_reduce = (const float*)d_in[t];
        else if (in_sizes[t] == 256 * 528)         w_recover = (const float*)d_in[t];
    }
    if (!x) x = (const float*)d_in[0];
    if (!w_reduce) w_reduce = (const float*)d_in[1];
    if (!w_recover) w_recover = (const float*)d_in[2];

    float* out = (float*)d_out;
    bilinear_gate_kernel<<<576, 256>>>(x, w_reduce, w_recover, out);
}